// round 7
// baseline (speedup 1.0000x reference)
#include <cuda_runtime.h>
#include <cuda_bf16.h>
#include <math.h>

// ---------------------------------------------------------------------------
// Problem constants
// ---------------------------------------------------------------------------
#define B_   512
#define T_   100
#define X_   38
#define Z_   3
#define H_   500
#define G_   1500      // 3*H
#define L_   20
#define BT_  51200     // B*T
#define AM_  51200     // activation matrix "M" (row length of K-major tensors)

// Output layout: tuple flattened in reference order
#define OFF_XMU   0u
#define OFF_XSTD  1945600u   // BT*38
#define OFF_ZGEN  3891200u
#define OFF_ZFIN  4044800u
#define OFF_ZMU   4198400u
#define OFF_ZSTD  4352000u
#define OFF_LDJ   4505600u

// ---------------------------------------------------------------------------
// Scratch (device globals; no runtime allocation)
// ---------------------------------------------------------------------------
__device__ float g_xT[(size_t)X_ * AM_];      // [38][51200]
__device__ float g_gi[(size_t)G_ * AM_];      // [1500][51200]
__device__ float g_hK[(size_t)512 * AM_];     // GRU h history, k-padded to 512 rows
__device__ float g_t1[(size_t)H_ * AM_];      // [500][51200]
__device__ float g_hp[(size_t)H_ * AM_];      // enc: row-major TB; dec: K-major
// K-major padded weights (pad columns hold garbage; guarded in epilogues)
__device__ float g_wtgi[(size_t)X_ * 1536];   // [38][1536]
__device__ float g_wt1[(size_t)H_ * 512];
__device__ float g_wt2[(size_t)H_ * 512];
__device__ float g_wt3[(size_t)H_ * 512];
__device__ float g_wt4[(size_t)H_ * 512];
__device__ float g_wth[(size_t)H_ * 128];     // heads: cols 0..37 xm, 38..75 xs
__device__ unsigned g_bar_cnt;
__device__ unsigned g_bar_sense;

// ---------------------------------------------------------------------------
// helpers
// ---------------------------------------------------------------------------
typedef unsigned long long u64;

__device__ __forceinline__ u64 dup2(float x) {
    u64 r;
    unsigned xi = __float_as_uint(x);
    asm("mov.b64 %0, {%1,%2};" : "=l"(r) : "r"(xi), "r"(xi));
    return r;
}
__device__ __forceinline__ void fma2(u64& d, u64 a, u64 b) {
    asm("fma.rn.f32x2 %0, %1, %2, %0;" : "+l"(d) : "l"(a), "l"(b));
}
__device__ __forceinline__ void up2(u64 v, float& lo, float& hi) {
    unsigned l, h;
    asm("mov.b64 {%0,%1}, %2;" : "=r"(l), "=r"(h) : "l"(v));
    lo = __uint_as_float(l); hi = __uint_as_float(h);
}
__device__ __forceinline__ float softplusf(float x) {
    return (x > 20.f) ? x : log1pf(expf(x));
}
__device__ __forceinline__ float sigmoidf(float x) {
    return 1.f / (1.f + expf(-x));
}

__device__ __forceinline__ void cp16(void* sdst, const void* gsrc, int src_bytes) {
    unsigned s = (unsigned)__cvta_generic_to_shared(sdst);
    asm volatile("cp.async.ca.shared.global [%0], [%1], 16, %2;"
                 :: "r"(s), "l"(gsrc), "r"(src_bytes) : "memory");
}
__device__ __forceinline__ void cp_commit() {
    asm volatile("cp.async.commit_group;" ::: "memory");
}
template<int N>
__device__ __forceinline__ void cp_wait() {
    asm volatile("cp.async.wait_group %0;" :: "n"(N) : "memory");
}

// ---------------------------------------------------------------------------
// Self-resetting grid barrier (replay-safe: sense is monotonic).
// ---------------------------------------------------------------------------
__device__ __forceinline__ void grid_bar(int nct) {
    __syncthreads();
    if (threadIdx.x == 0) {
        __threadfence();
        unsigned s0 = *(volatile unsigned*)&g_bar_sense;
        unsigned old = atomicAdd(&g_bar_cnt, 1u);
        if (old == (unsigned)(nct - 1)) {
            *(volatile unsigned*)&g_bar_cnt = 0u;
            __threadfence();
            atomicAdd(&g_bar_sense, 1u);
        } else {
            while (*(volatile unsigned*)&g_bar_sense == s0) __nanosleep(64);
        }
        __threadfence();
    }
    __syncthreads();
}

// ---------------------------------------------------------------------------
// x transpose: x[B][T][38] -> xT[38][T*512+b]
// ---------------------------------------------------------------------------
__global__ __launch_bounds__(256) void transpose_x(const float* __restrict__ x,
                                                   float* __restrict__ xT) {
    int idx = blockIdx.x * 256 + threadIdx.x;
    if (idx >= X_ * AM_) return;
    int kx = idx / AM_;
    int r  = idx % AM_;
    int t = r >> 9, b = r & 511;
    xT[idx] = x[((size_t)b * T_ + t) * X_ + kx];
}

// ---------------------------------------------------------------------------
// Weight transpose with padded output stride + column offset:
//   out[c][coff + r] = in[r][c],  out row pitch = ostride
// ---------------------------------------------------------------------------
__global__ void transpose_pad(const float* __restrict__ in, float* __restrict__ out,
                              int R, int C, int ostride, int coff) {
    __shared__ float tile[32][33];
    int c0 = blockIdx.x * 32, r0 = blockIdx.y * 32;
    int tx = threadIdx.x, ty = threadIdx.y;  // 32 x 8
    for (int i = ty; i < 32; i += 8) {
        int r = r0 + i, c = c0 + tx;
        tile[i][tx] = (r < R && c < C) ? in[(size_t)r * C + c] : 0.f;
    }
    __syncthreads();
    for (int i = ty; i < 32; i += 8) {
        int c = c0 + i, r = r0 + tx;
        if (c < C && r < R) out[(size_t)c * ostride + coff + r] = tile[tx][i];
    }
}

// ---------------------------------------------------------------------------
// cp.async double-buffered GEMM, both operands K-major:
//   C = act(A^T[K][M] x W^T[K][Npad] + bias)
// BM=BN=128, BK=8, 256 threads, 8x8/thread, f32x2 accumulation, 2 CTAs/SM.
// OUTK=1: C K-major [N][M]; OUTK=0: C row-major [M][N].
// ---------------------------------------------------------------------------
template<int ACT>
__device__ __forceinline__ float epi(float v) {
    if (ACT == 1) return v > 0.f ? v : 0.1f * v;
    if (ACT == 2) return softplusf(v) + 1e-4f;
    return v;
}

template<int ACT, int OUTK>
__global__ __launch_bounds__(256, 2) void gemm2t(
    const float* __restrict__ AT, const float* __restrict__ WT,
    const float* __restrict__ bias, float* __restrict__ C,
    int M, int N, int K, int NPAD)
{
    __shared__ __align__(16) float As[2][8][128];
    __shared__ __align__(16) float Ws[2][8][128];
    const int tid = threadIdx.x;
    const int m0 = blockIdx.x * 128;
    const int n0 = blockIdx.y * 128;
    const int tx = tid & 15, ty = tid >> 4;
    const int ka = tid >> 5, ca = (tid & 31) * 4;

    u64 acc[8][4];
#pragma unroll
    for (int i = 0; i < 8; i++)
#pragma unroll
        for (int j = 0; j < 4; j++) acc[i][j] = 0ULL;

    auto issue = [&](int buf, int k0) {
        int k = k0 + ka;
        int kc = (k < K) ? k : (K - 1);
        int nb = (k < K) ? 16 : 0;
        cp16(&As[buf][ka][ca], AT + (size_t)kc * M + m0 + ca, nb);
        cp16(&Ws[buf][ka][ca], WT + (size_t)kc * NPAD + n0 + ca, nb);
    };

    issue(0, 0); cp_commit();
    cp_wait<0>(); __syncthreads();

    const int nt = (K + 7) / 8;
    int buf = 0;
    for (int it = 0; it < nt; it++) {
        const bool more = (it + 1) < nt;
        if (more) { issue(buf ^ 1, (it + 1) * 8); cp_commit(); }
        const float (*Ac)[128] = As[buf];
        const float (*Wc)[128] = Ws[buf];
#pragma unroll
        for (int kk = 0; kk < 8; kk++) {
            float4 a0 = *(const float4*)&Ac[kk][ty * 8];
            float4 a1 = *(const float4*)&Ac[kk][ty * 8 + 4];
            const longlong2* wp = (const longlong2*)&Wc[kk][tx * 8];
            longlong2 bA = wp[0], bB = wp[1];
            u64 ad[8] = { dup2(a0.x), dup2(a0.y), dup2(a0.z), dup2(a0.w),
                          dup2(a1.x), dup2(a1.y), dup2(a1.z), dup2(a1.w) };
            u64 bp[4] = { (u64)bA.x, (u64)bA.y, (u64)bB.x, (u64)bB.y };
#pragma unroll
            for (int i = 0; i < 8; i++)
#pragma unroll
                for (int j = 0; j < 4; j++) fma2(acc[i][j], ad[i], bp[j]);
        }
        if (more) { cp_wait<0>(); __syncthreads(); }
        buf ^= 1;
    }

    float cv[8][8];
#pragma unroll
    for (int i = 0; i < 8; i++)
#pragma unroll
        for (int jp = 0; jp < 4; jp++) up2(acc[i][jp], cv[i][jp * 2], cv[i][jp * 2 + 1]);

    if (OUTK) {
#pragma unroll
        for (int jn = 0; jn < 8; jn++) {
            int n = n0 + tx * 8 + jn;
            if (n < N) {
                float bb = bias[n];
                float4 o0, o1;
                o0.x = epi<ACT>(cv[0][jn] + bb); o0.y = epi<ACT>(cv[1][jn] + bb);
                o0.z = epi<ACT>(cv[2][jn] + bb); o0.w = epi<ACT>(cv[3][jn] + bb);
                o1.x = epi<ACT>(cv[4][jn] + bb); o1.y = epi<ACT>(cv[5][jn] + bb);
                o1.z = epi<ACT>(cv[6][jn] + bb); o1.w = epi<ACT>(cv[7][jn] + bb);
                size_t base = (size_t)n * M + m0 + ty * 8;
                *(float4*)(C + base)     = o0;
                *(float4*)(C + base + 4) = o1;
            }
        }
    } else {
#pragma unroll
        for (int i = 0; i < 8; i++) {
            size_t m = (size_t)(m0 + ty * 8 + i);
            float* crow = C + m * (size_t)N;
            int nb = n0 + tx * 8;
#pragma unroll
            for (int jn = 0; jn < 8; jn++) {
                int n = nb + jn;
                if (n < N) crow[n] = epi<ACT>(cv[i][jn] + bias[n]);
            }
        }
    }
}

// ---------------------------------------------------------------------------
// Fused output heads on K-major A with combined K-major head weights
// WTh[500][128] (cols 0..37 xm, 38..75 xs). Writes [b][t][38] into d_out.
// ---------------------------------------------------------------------------
__global__ __launch_bounds__(256, 2) void head_gemm(
    const float* __restrict__ AT, const float* __restrict__ WTh,
    const float* __restrict__ bm, const float* __restrict__ bs,
    float* __restrict__ Cm, float* __restrict__ Cs)
{
    __shared__ __align__(16) float As[2][8][128];
    __shared__ __align__(16) float Ws[2][8][128];
    const int tid = threadIdx.x;
    const int m0 = blockIdx.x * 128;
    const int tx = tid & 15, ty = tid >> 4;
    const int ka = tid >> 5, ca = (tid & 31) * 4;
    const int K = H_;

    u64 acc[8][4];
#pragma unroll
    for (int i = 0; i < 8; i++)
#pragma unroll
        for (int j = 0; j < 4; j++) acc[i][j] = 0ULL;

    auto issue = [&](int buf, int k0) {
        int k = k0 + ka;
        int kc = (k < K) ? k : (K - 1);
        int nb = (k < K) ? 16 : 0;
        cp16(&As[buf][ka][ca], AT + (size_t)kc * AM_ + m0 + ca, nb);
        cp16(&Ws[buf][ka][ca], WTh + (size_t)kc * 128 + ca, nb);
    };

    issue(0, 0); cp_commit();
    cp_wait<0>(); __syncthreads();

    const int nt = (K + 7) / 8;
    int buf = 0;
    for (int it = 0; it < nt; it++) {
        const bool more = (it + 1) < nt;
        if (more) { issue(buf ^ 1, (it + 1) * 8); cp_commit(); }
        const float (*Ac)[128] = As[buf];
        const float (*Wc)[128] = Ws[buf];
#pragma unroll
        for (int kk = 0; kk < 8; kk++) {
            float4 a0 = *(const float4*)&Ac[kk][ty * 8];
            float4 a1 = *(const float4*)&Ac[kk][ty * 8 + 4];
            const longlong2* wp = (const longlong2*)&Wc[kk][tx * 8];
            longlong2 bA = wp[0], bB = wp[1];
            u64 ad[8] = { dup2(a0.x), dup2(a0.y), dup2(a0.z), dup2(a0.w),
                          dup2(a1.x), dup2(a1.y), dup2(a1.z), dup2(a1.w) };
            u64 bp[4] = { (u64)bA.x, (u64)bA.y, (u64)bB.x, (u64)bB.y };
#pragma unroll
            for (int i = 0; i < 8; i++)
#pragma unroll
                for (int j = 0; j < 4; j++) fma2(acc[i][j], ad[i], bp[j]);
        }
        if (more) { cp_wait<0>(); __syncthreads(); }
        buf ^= 1;
    }

#pragma unroll
    for (int i = 0; i < 8; i++) {
        int mp = m0 + ty * 8 + i;
        int b = mp & 511, t = mp >> 9;
        size_t base = ((size_t)b * T_ + t) * 38;
#pragma unroll
        for (int jp = 0; jp < 4; jp++) {
            float c0v, c1v; up2(acc[i][jp], c0v, c1v);
            int nn = tx * 8 + jp * 2;
            if (nn < 38) {
                Cm[base + nn]     = c0v + bm[nn];
                Cm[base + nn + 1] = c1v + bm[nn + 1];
            } else if (nn < 76) {
                Cs[base + nn - 38] = softplusf(c0v + bs[nn - 38]) + 1e-4f;
                Cs[base + nn - 37] = softplusf(c1v + bs[nn - 37]) + 1e-4f;
            }
        }
    }
}

// ---------------------------------------------------------------------------
// GRU v5: persistent grid-stepped GEMM, 2 CTAs/SM for latency hiding.
// Grid 256 = 4 m-tiles x 64 j-tiles; CTA tile: 128 batch x 8 gate-triplets;
// 1 gate-triplet per warp, 4 batch per lane. SMEM weights [24][512] loaded
// once; cp.async double-buffered h tiles (32k x 128b); 16 syncs/step;
// one grid barrier per step.
// ---------------------------------------------------------------------------
#define GRU_SMEM (24 * 512 + 2 * 32 * 132)   // floats = 82,944 B

template<int DEC>
__global__ __launch_bounds__(256, 2) void gru4(
    const float* __restrict__ gi_or_z,
    const float* __restrict__ Whh, const float* __restrict__ bhh,
    const float* __restrict__ wih, const float* __restrict__ bih,
    float* __restrict__ hout)
{
    extern __shared__ float smem[];
    float* sw = smem;                 // [24][512]   row = g*8 + jl
    float* sA = smem + 24 * 512;      // [2][32][132]

    const int tid = threadIdx.x;
    const int jj  = tid >> 5;         // warp 0..7 -> local j
    const int mg  = tid & 31;         // lane -> 4 batch elems
    const int jt  = blockIdx.x & 63;
    const int mt  = blockIdx.x >> 6;
    const int j0  = jt * 8;
    const int m0  = mt * 128;
    const int j   = j0 + jj;
    const bool act = j < H_;
    const int lrow = tid >> 3;        // 0..31 staging row
    const int lcol = (tid & 7) * 16;  // staging col

    // ---- weights to smem (once); pads zero-filled ----
    for (int idx = tid; idx < 24 * 128; idx += 256) {
        int row = idx >> 7;            // g*8 + jl
        int k4  = (idx & 127) * 4;
        int g = row >> 3, jl = row & 7;
        int jw = j0 + jl;
        float4 v = make_float4(0.f, 0.f, 0.f, 0.f);
        if (jw < H_ && k4 < H_)
            v = *(const float4*)(Whh + ((size_t)(g * H_ + jw)) * H_ + k4);
        *(float4*)&sw[row * 512 + k4] = v;
    }

    // ---- per-thread constants ----
    float br = 0.f, bz = 0.f, bn = 0.f;
    float wi[9], bi[3];
#pragma unroll
    for (int i = 0; i < 9; i++) wi[i] = 0.f;
#pragma unroll
    for (int i = 0; i < 3; i++) bi[i] = 0.f;
    if (act) {
        br = bhh[j]; bz = bhh[j + H_]; bn = bhh[j + 2 * H_];
        if (DEC) {
            bi[0] = bih[j]; bi[1] = bih[j + H_]; bi[2] = bih[j + 2 * H_];
#pragma unroll
            for (int d = 0; d < 3; d++) {
                wi[d]     = wih[(size_t)j * 3 + d];
                wi[3 + d] = wih[(size_t)(j + H_) * 3 + d];
                wi[6 + d] = wih[(size_t)(j + 2 * H_) * 3 + d];
            }
        }
    }
    float hp4[4];
#pragma unroll
    for (int i = 0; i < 4; i++) hp4[i] = 0.f;
    __syncthreads();

    for (int t = 0; t < T_; t++) {
        // ---- input-gate values ig[gate][m] ----
        float ig[3][4];
        if (!DEC) {
            size_t off = (size_t)t * 512 + m0 + mg * 4;
#pragma unroll
            for (int g = 0; g < 3; g++) {
                float4 v = act ? *(const float4*)(gi_or_z + (size_t)(g * H_ + j) * AM_ + off)
                               : make_float4(0.f, 0.f, 0.f, 0.f);
                ig[g][0] = v.x; ig[g][1] = v.y; ig[g][2] = v.z; ig[g][3] = v.w;
            }
        } else {
#pragma unroll
            for (int i = 0; i < 4; i++) {
                int b = m0 + mg * 4 + i;
                const float* zp = gi_or_z + ((size_t)b * T_ + t) * 3;
                float z0 = zp[0], z1 = zp[1], z2 = zp[2];
#pragma unroll
                for (int g = 0; g < 3; g++)
                    ig[g][i] = bi[g] + wi[3 * g] * z0 + wi[3 * g + 1] * z1 + wi[3 * g + 2] * z2;
            }
        }

        u64 acc[3][2];
#pragma unroll
        for (int g = 0; g < 3; g++) { acc[g][0] = 0ULL; acc[g][1] = 0ULL; }

        if (t > 0) {
            const float* Asrc = hout + (size_t)(t - 1) * 512 + m0;
            auto issueT = [&](int buf, int kt) {
                const float* p = Asrc + (size_t)(kt * 32 + lrow) * AM_ + lcol;
                float* q = &sA[buf * 32 * 132 + lrow * 132 + lcol];
                cp16(q,      p,      16);
                cp16(q + 4,  p + 4,  16);
                cp16(q + 8,  p + 8,  16);
                cp16(q + 12, p + 12, 16);
            };
            issueT(0, 0); cp_commit();
            cp_wait<0>(); __syncthreads();
            int buf = 0;
#pragma unroll 1
            for (int kt = 0; kt < 16; kt++) {
                const bool more = kt < 15;
                if (more) { issueT(buf ^ 1, kt + 1); cp_commit(); }
                const float* Ab = &sA[buf * 32 * 132];
#pragma unroll
                for (int kk = 0; kk < 32; kk += 4) {
                    int kb = kt * 32 + kk;
                    float4 wr = *(const float4*)&sw[jj * 512 + kb];
                    float4 wz = *(const float4*)&sw[(8 + jj) * 512 + kb];
                    float4 wn = *(const float4*)&sw[(16 + jj) * 512 + kb];
#pragma unroll
                    for (int i = 0; i < 4; i++) {
                        longlong2 hv = *(const longlong2*)&Ab[(kk + i) * 132 + mg * 4];
                        u64 h0 = (u64)hv.x, h1 = (u64)hv.y;
                        u64 d;
                        d = dup2(((const float*)&wr)[i]); fma2(acc[0][0], h0, d); fma2(acc[0][1], h1, d);
                        d = dup2(((const float*)&wz)[i]); fma2(acc[1][0], h0, d); fma2(acc[1][1], h1, d);
                        d = dup2(((const float*)&wn)[i]); fma2(acc[2][0], h0, d); fma2(acc[2][1], h1, d);
                    }
                }
                if (more) cp_wait<0>();
                __syncthreads();
                buf ^= 1;
            }
        }

        // ---- epilogue ----
        float aR[4], aZ[4], aN[4];
        up2(acc[0][0], aR[0], aR[1]); up2(acc[0][1], aR[2], aR[3]);
        up2(acc[1][0], aZ[0], aZ[1]); up2(acc[1][1], aZ[2], aZ[3]);
        up2(acc[2][0], aN[0], aN[1]); up2(acc[2][1], aN[2], aN[3]);

        if (act) {
            float4 hv;
#pragma unroll
            for (int i = 0; i < 4; i++) {
                float r  = sigmoidf(ig[0][i] + aR[i] + br);
                float zg = sigmoidf(ig[1][i] + aZ[i] + bz);
                float n  = tanhf(ig[2][i] + r * (aN[i] + bn));
                float hn = (1.f - zg) * n + zg * hp4[i];
                hp4[i] = hn;
                ((float*)&hv)[i] = hn;
            }
            *(float4*)(hout + (size_t)j * AM_ + (size_t)t * 512 + m0 + mg * 4) = hv;
        }

        if (t < T_ - 1) {
            __threadfence();
            grid_bar(gridDim.x);
        }
    }
}

// ---------------------------------------------------------------------------
// Latent scan: one warp per batch element; hp row-major TB [t*512+b][500].
// ---------------------------------------------------------------------------
__global__ __launch_bounds__(128) void latent_kernel(
    const float* __restrict__ hp, const float* __restrict__ eps,
    const float* __restrict__ zmW, const float* __restrict__ zmb,
    const float* __restrict__ zsW, const float* __restrict__ zsb,
    float* __restrict__ out)
{
    __shared__ float s_m[3 * 503], s_s[3 * 503], s_mb[3], s_sb[3];
    const int tid = threadIdx.x;
    for (int i = tid; i < 3 * 503; i += 128) { s_m[i] = zmW[i]; s_s[i] = zsW[i]; }
    if (tid < 3) { s_mb[tid] = zmb[tid]; s_sb[tid] = zsb[tid]; }
    __syncthreads();

    const int warp = tid >> 5, lane = tid & 31;
    const int b = blockIdx.x * 4 + warp;
    if (b >= B_) return;

    float z0 = 0.f, z1 = 0.f, z2 = 0.f;
    float* zg = out + OFF_ZGEN;
    float* zm = out + OFF_ZMU;
    float* zs = out + OFF_ZSTD;

    for (int t = 0; t < T_; t++) {
        float m0 = 0.f, m1 = 0.f, m2 = 0.f, s0 = 0.f, s1 = 0.f, s2 = 0.f;
        const float* hrow = hp + ((size_t)t * 512 + b) * H_;
        for (int jj = lane; jj < 503; jj += 32) {
            float v = (jj < 500) ? hrow[jj] : (jj == 500 ? z0 : (jj == 501 ? z1 : z2));
            m0 += v * s_m[jj]; m1 += v * s_m[503 + jj]; m2 += v * s_m[1006 + jj];
            s0 += v * s_s[jj]; s1 += v * s_s[503 + jj]; s2 += v * s_s[1006 + jj];
        }
#pragma unroll
        for (int o = 16; o > 0; o >>= 1) {
            m0 += __shfl_xor_sync(0xffffffffu, m0, o);
            m1 += __shfl_xor_sync(0xffffffffu, m1, o);
            m2 += __shfl_xor_sync(0xffffffffu, m2, o);
            s0 += __shfl_xor_sync(0xffffffffu, s0, o);
            s1 += __shfl_xor_sync(0xffffffffu, s1, o);
            s2 += __shfl_xor_sync(0xffffffffu, s2, o);
        }
        m0 += s_mb[0]; m1 += s_mb[1]; m2 += s_mb[2];
        float st0 = softplusf(s0 + s_sb[0]) + 1e-4f;
        float st1 = softplusf(s1 + s_sb[1]) + 1e-4f;
        float st2 = softplusf(s2 + s_sb[2]) + 1e-4f;
        size_t er = ((size_t)b * T_ + t) * 3;
        float e0 = eps[er], e1 = eps[er + 1], e2 = eps[er + 2];
        z0 = m0 + st0 * e0; z1 = m1 + st1 * e1; z2 = m2 + st2 * e2;
        if (lane == 0) {
            zg[er] = z0; zg[er + 1] = z1; zg[er + 2] = z2;
            zm[er] = m0; zm[er + 1] = m1; zm[er + 2] = m2;
            zs[er] = st0; zs[er + 1] = st1; zs[er + 2] = st2;
        }
    }
}

// ---------------------------------------------------------------------------
// Planar flow stack
// ---------------------------------------------------------------------------
__global__ __launch_bounds__(256) void flow_kernel(
    const float* __restrict__ fw, const float* __restrict__ fb,
    const float* __restrict__ fu, float* __restrict__ out)
{
    __shared__ float sw[L_][3], su[L_][3], sb[L_], suw[L_];
    const int tid = threadIdx.x;
    if (tid < L_) {
        float w0 = fw[tid * 3], w1 = fw[tid * 3 + 1], w2 = fw[tid * 3 + 2];
        float u0 = fu[tid * 3], u1 = fu[tid * 3 + 1], u2 = fu[tid * 3 + 2];
        float wu = w0 * u0 + w1 * u1 + w2 * u2;
        float m = -1.f + softplusf(wu);
        float ww = w0 * w0 + w1 * w1 + w2 * w2 + 1e-7f;
        float c = (m - wu) / ww;
        sw[tid][0] = w0; sw[tid][1] = w1; sw[tid][2] = w2;
        su[tid][0] = u0 + c * w0; su[tid][1] = u1 + c * w1; su[tid][2] = u2 + c * w2;
        sb[tid] = fb[tid];
        suw[tid] = su[tid][0] * w0 + su[tid][1] * w1 + su[tid][2] * w2;
    }
    __syncthreads();
    int idx = blockIdx.x * 256 + tid;
    if (idx >= BT_) return;
    const float* zg = out + OFF_ZGEN;
    float z0 = zg[idx * 3], z1 = zg[idx * 3 + 1], z2 = zg[idx * 3 + 2];
    float ld = 0.f;
#pragma unroll
    for (int l = 0; l < L_; l++) {
        float lin = z0 * sw[l][0] + z1 * sw[l][1] + z2 * sw[l][2] + sb[l];
        float th = tanhf(lin);
        z0 += su[l][0] * th; z1 += su[l][1] * th; z2 += su[l][2] * th;
        float det = 1.f + (1.f - th * th) * suw[l];
        ld += logf(fabsf(det) + 1e-7f);
    }
    float* zf = out + OFF_ZFIN;
    zf[idx * 3] = z0; zf[idx * 3 + 1] = z1; zf[idx * 3 + 2] = z2;
    out[OFF_LDJ + idx] = ld;
}

// ---------------------------------------------------------------------------
// Launch
// ---------------------------------------------------------------------------
extern "C" void kernel_launch(void* const* d_in, const int* in_sizes, int n_in,
                              void* d_out, int out_size) {
    (void)in_sizes; (void)n_in; (void)out_size;
    const float* x        = (const float*)d_in[0];
    const float* eps      = (const float*)d_in[1];
    const float* enc_Wih  = (const float*)d_in[2];
    const float* enc_Whh  = (const float*)d_in[3];
    const float* enc_bih  = (const float*)d_in[4];
    const float* enc_bhh  = (const float*)d_in[5];
    const float* enc_W1   = (const float*)d_in[6];
    const float* enc_b1   = (const float*)d_in[7];
    const float* enc_W2   = (const float*)d_in[8];
    const float* enc_b2   = (const float*)d_in[9];
    const float* zm_W     = (const float*)d_in[10];
    const float* zm_b     = (const float*)d_in[11];
    const float* zs_W     = (const float*)d_in[12];
    const float* zs_b     = (const float*)d_in[13];
    const float* flow_w   = (const float*)d_in[14];
    const float* flow_b   = (const float*)d_in[15];
    const float* flow_u   = (const float*)d_in[16];
    const float* dec_Wih  = (const float*)d_in[17];
    const float* dec_Whh  = (const float*)d_in[18];
    const float* dec_bih  = (const float*)d_in[19];
    const float* dec_bhh  = (const float*)d_in[20];
    const float* dec_W1   = (const float*)d_in[21];
    const float* dec_b1   = (const float*)d_in[22];
    const float* dec_W2   = (const float*)d_in[23];
    const float* dec_b2   = (const float*)d_in[24];
    const float* xm_W     = (const float*)d_in[25];
    const float* xm_b     = (const float*)d_in[26];
    const float* xs_W     = (const float*)d_in[27];
    const float* xs_b     = (const float*)d_in[28];
    float* out = (float*)d_out;

    float *xT, *gi, *hK, *t1, *hp, *wtgi, *wt1, *wt2, *wt3, *wt4, *wth;
    cudaGetSymbolAddress((void**)&xT,   g_xT);
    cudaGetSymbolAddress((void**)&gi,   g_gi);
    cudaGetSymbolAddress((void**)&hK,   g_hK);
    cudaGetSymbolAddress((void**)&t1,   g_t1);
    cudaGetSymbolAddress((void**)&hp,   g_hp);
    cudaGetSymbolAddress((void**)&wtgi, g_wtgi);
    cudaGetSymbolAddress((void**)&wt1,  g_wt1);
    cudaGetSymbolAddress((void**)&wt2,  g_wt2);
    cudaGetSymbolAddress((void**)&wt3,  g_wt3);
    cudaGetSymbolAddress((void**)&wt4,  g_wt4);
    cudaGetSymbolAddress((void**)&wth,  g_wth);

    const size_t gru_smem = GRU_SMEM * sizeof(float);
    cudaFuncSetAttribute(gru4<0>, cudaFuncAttributeMaxDynamicSharedMemorySize, (int)gru_smem);
    cudaFuncSetAttribute(gru4<1>, cudaFuncAttributeMaxDynamicSharedMemorySize, (int)gru_smem);

    // zero k-pad rows 500..511 of h history
    cudaMemsetAsync(hK + (size_t)H_ * AM_, 0, (size_t)12 * AM_ * sizeof(float));

    dim3 tb(32, 8);
    // ---- weight transposes (K-major, padded) ----
    transpose_pad<<<dim3(2, 47),  tb>>>(enc_Wih, wtgi, G_, X_, 1536, 0);
    transpose_pad<<<dim3(16, 16), tb>>>(enc_W1, wt1, H_, H_, 512, 0);
    transpose_pad<<<dim3(16, 16), tb>>>(enc_W2, wt2, H_, H_, 512, 0);
    transpose_pad<<<dim3(16, 16), tb>>>(dec_W1, wt3, H_, H_, 512, 0);
    transpose_pad<<<dim3(16, 16), tb>>>(dec_W2, wt4, H_, H_, 512, 0);
    transpose_pad<<<dim3(16, 2),  tb>>>(xm_W, wth, X_, H_, 128, 0);
    transpose_pad<<<dim3(16, 2),  tb>>>(xs_W, wth, X_, H_, 128, 38);
    transpose_x<<<(X_ * AM_ + 255) / 256, 256>>>(x, xT);

    // ---- Encoder ----
    gemm2t<0, 1><<<dim3(400, 12), 256>>>(xT, wtgi, enc_bih, gi, AM_, G_, X_, 1536);
    gru4<0><<<256, 256, gru_smem>>>(gi, enc_Whh, enc_bhh, nullptr, nullptr, hK);
    gemm2t<1, 1><<<dim3(400, 4), 256>>>(hK, wt1, enc_b1, t1, AM_, H_, H_, 512);
    gemm2t<1, 0><<<dim3(400, 4), 256>>>(t1, wt2, enc_b2, hp, AM_, H_, H_, 512);

    // ---- Latent scan + flows ----
    latent_kernel<<<128, 128>>>(hp, eps, zm_W, zm_b, zs_W, zs_b, out);
    flow_kernel<<<200, 256>>>(flow_w, flow_b, flow_u, out);

    // ---- Decoder (input gates inline from z_fin) ----
    gru4<1><<<256, 256, gru_smem>>>(out + OFF_ZFIN, dec_Whh, dec_bhh, dec_Wih, dec_bih, hK);
    gemm2t<1, 1><<<dim3(400, 4), 256>>>(hK, wt3, dec_b1, t1, AM_, H_, H_, 512);
    gemm2t<1, 1><<<dim3(400, 4), 256>>>(t1, wt4, dec_b2, hp, AM_, H_, H_, 512);

    // ---- Output heads ----
    head_gemm<<<400, 256>>>(hp, wth, xm_b, xs_b, out + OFF_XMU, out + OFF_XSTD);
}

// round 8
// speedup vs baseline: 1.2578x; 1.2578x over previous
#include <cuda_runtime.h>
#include <cuda_bf16.h>
#include <math.h>

// ---------------------------------------------------------------------------
// Problem constants
// ---------------------------------------------------------------------------
#define B_   512
#define T_   100
#define X_   38
#define Z_   3
#define H_   500
#define G_   1500      // 3*H
#define L_   20
#define BT_  51200     // B*T
#define AM_  51200     // activation matrix "M" (row length of K-major tensors)

// Output layout: tuple flattened in reference order
#define OFF_XMU   0u
#define OFF_XSTD  1945600u   // BT*38
#define OFF_ZGEN  3891200u
#define OFF_ZFIN  4044800u
#define OFF_ZMU   4198400u
#define OFF_ZSTD  4352000u
#define OFF_LDJ   4505600u

// ---------------------------------------------------------------------------
// Scratch (device globals; no runtime allocation)
// ---------------------------------------------------------------------------
__device__ float g_xT[(size_t)X_ * AM_];      // [38][51200]
__device__ float g_gi[(size_t)G_ * AM_];      // [1500][51200]
__device__ float g_hK[(size_t)512 * AM_];     // GRU h history, k-padded to 512 rows
__device__ float g_t1[(size_t)H_ * AM_];      // [500][51200]
__device__ float g_hp[(size_t)H_ * AM_];      // enc: row-major TB; dec: K-major
// K-major padded weights (pad columns hold garbage; guarded in epilogues)
__device__ float g_wtgi[(size_t)X_ * 1536];   // [38][1536]
__device__ float g_wt1[(size_t)H_ * 512];
__device__ float g_wt2[(size_t)H_ * 512];
__device__ float g_wt3[(size_t)H_ * 512];
__device__ float g_wt4[(size_t)H_ * 512];
__device__ float g_wth[(size_t)H_ * 128];     // heads: cols 0..37 xm, 38..75 xs
__device__ unsigned g_flag[128];              // per-CTA step flags (zeroed per GRU)

// ---------------------------------------------------------------------------
// helpers
// ---------------------------------------------------------------------------
typedef unsigned long long u64;

__device__ __forceinline__ u64 dup2(float x) {
    u64 r;
    unsigned xi = __float_as_uint(x);
    asm("mov.b64 %0, {%1,%2};" : "=l"(r) : "r"(xi), "r"(xi));
    return r;
}
__device__ __forceinline__ void fma2(u64& d, u64 a, u64 b) {
    asm("fma.rn.f32x2 %0, %1, %2, %0;" : "+l"(d) : "l"(a), "l"(b));
}
__device__ __forceinline__ void up2(u64 v, float& lo, float& hi) {
    unsigned l, h;
    asm("mov.b64 {%0,%1}, %2;" : "=r"(l), "=r"(h) : "l"(v));
    lo = __uint_as_float(l); hi = __uint_as_float(h);
}
__device__ __forceinline__ float softplusf(float x) {
    return (x > 20.f) ? x : log1pf(expf(x));
}
__device__ __forceinline__ float sigmoidf(float x) {
    return 1.f / (1.f + expf(-x));
}

__device__ __forceinline__ void cp16(void* sdst, const void* gsrc, int src_bytes) {
    unsigned s = (unsigned)__cvta_generic_to_shared(sdst);
    asm volatile("cp.async.ca.shared.global [%0], [%1], 16, %2;"
                 :: "r"(s), "l"(gsrc), "r"(src_bytes) : "memory");
}
__device__ __forceinline__ void cp_commit() {
    asm volatile("cp.async.commit_group;" ::: "memory");
}
template<int N>
__device__ __forceinline__ void cp_wait() {
    asm volatile("cp.async.wait_group %0;" :: "n"(N) : "memory");
}

__device__ __forceinline__ void flag_store_release(unsigned* p, unsigned v) {
    asm volatile("st.release.gpu.global.u32 [%0], %1;" :: "l"(p), "r"(v) : "memory");
}
__device__ __forceinline__ unsigned flag_load_acquire(const unsigned* p) {
    unsigned v;
    asm volatile("ld.acquire.gpu.global.u32 %0, [%1];" : "=r"(v) : "l"(p));
    return v;
}

// ---------------------------------------------------------------------------
// x transpose: x[B][T][38] -> xT[38][T*512+b]
// ---------------------------------------------------------------------------
__global__ __launch_bounds__(256) void transpose_x(const float* __restrict__ x,
                                                   float* __restrict__ xT) {
    int idx = blockIdx.x * 256 + threadIdx.x;
    if (idx >= X_ * AM_) return;
    int kx = idx / AM_;
    int r  = idx % AM_;
    int t = r >> 9, b = r & 511;
    xT[idx] = x[((size_t)b * T_ + t) * X_ + kx];
}

// ---------------------------------------------------------------------------
// All weight transposes in one launch. blockIdx.z selects the tensor.
//   out[c][coff + r] = in[r][c], out row pitch = ostride
// ---------------------------------------------------------------------------
__global__ void transpose_all(
    const float* __restrict__ ewih, const float* __restrict__ w1,
    const float* __restrict__ w2,   const float* __restrict__ w3,
    const float* __restrict__ w4,   const float* __restrict__ xm,
    const float* __restrict__ xs,
    float* __restrict__ wtgi, float* __restrict__ wt1, float* __restrict__ wt2,
    float* __restrict__ wt3,  float* __restrict__ wt4, float* __restrict__ wth)
{
    __shared__ float tile[32][33];
    const float* in; float* out; int R, C, ostride, coff;
    switch (blockIdx.z) {
        case 0: in = ewih; out = wtgi; R = G_; C = X_; ostride = 1536; coff = 0;  break;
        case 1: in = w1;   out = wt1;  R = H_; C = H_; ostride = 512;  coff = 0;  break;
        case 2: in = w2;   out = wt2;  R = H_; C = H_; ostride = 512;  coff = 0;  break;
        case 3: in = w3;   out = wt3;  R = H_; C = H_; ostride = 512;  coff = 0;  break;
        case 4: in = w4;   out = wt4;  R = H_; C = H_; ostride = 512;  coff = 0;  break;
        case 5: in = xm;   out = wth;  R = X_; C = H_; ostride = 128;  coff = 0;  break;
        default:in = xs;   out = wth;  R = X_; C = H_; ostride = 128;  coff = 38; break;
    }
    int c0 = blockIdx.x * 32, r0 = blockIdx.y * 32;
    if (c0 >= C || r0 >= R) return;
    int tx = threadIdx.x, ty = threadIdx.y;  // 32 x 8
    for (int i = ty; i < 32; i += 8) {
        int r = r0 + i, c = c0 + tx;
        tile[i][tx] = (r < R && c < C) ? in[(size_t)r * C + c] : 0.f;
    }
    __syncthreads();
    for (int i = ty; i < 32; i += 8) {
        int c = c0 + i, r = r0 + tx;
        if (c < C && r < R) out[(size_t)c * ostride + coff + r] = tile[tx][i];
    }
}

// ---------------------------------------------------------------------------
// cp.async double-buffered GEMM, both operands K-major:
//   C = act(A^T[K][M] x W^T[K][Npad] + bias)
// BM=BN=128, BK=8, 256 threads, 8x8/thread, f32x2 accumulation, 2 CTAs/SM.
// OUTK=1: C K-major [N][M]; OUTK=0: C row-major [M][N].
// ---------------------------------------------------------------------------
template<int ACT>
__device__ __forceinline__ float epi(float v) {
    if (ACT == 1) return v > 0.f ? v : 0.1f * v;
    if (ACT == 2) return softplusf(v) + 1e-4f;
    return v;
}

template<int ACT, int OUTK>
__global__ __launch_bounds__(256, 2) void gemm2t(
    const float* __restrict__ AT, const float* __restrict__ WT,
    const float* __restrict__ bias, float* __restrict__ C,
    int M, int N, int K, int NPAD)
{
    __shared__ __align__(16) float As[2][8][128];
    __shared__ __align__(16) float Ws[2][8][128];
    const int tid = threadIdx.x;
    const int m0 = blockIdx.x * 128;
    const int n0 = blockIdx.y * 128;
    const int tx = tid & 15, ty = tid >> 4;
    const int ka = tid >> 5, ca = (tid & 31) * 4;

    u64 acc[8][4];
#pragma unroll
    for (int i = 0; i < 8; i++)
#pragma unroll
        for (int j = 0; j < 4; j++) acc[i][j] = 0ULL;

    auto issue = [&](int buf, int k0) {
        int k = k0 + ka;
        int kc = (k < K) ? k : (K - 1);
        int nb = (k < K) ? 16 : 0;
        cp16(&As[buf][ka][ca], AT + (size_t)kc * M + m0 + ca, nb);
        cp16(&Ws[buf][ka][ca], WT + (size_t)kc * NPAD + n0 + ca, nb);
    };

    issue(0, 0); cp_commit();
    cp_wait<0>(); __syncthreads();

    const int nt = (K + 7) / 8;
    int buf = 0;
    for (int it = 0; it < nt; it++) {
        const bool more = (it + 1) < nt;
        if (more) { issue(buf ^ 1, (it + 1) * 8); cp_commit(); }
        const float (*Ac)[128] = As[buf];
        const float (*Wc)[128] = Ws[buf];
#pragma unroll
        for (int kk = 0; kk < 8; kk++) {
            float4 a0 = *(const float4*)&Ac[kk][ty * 8];
            float4 a1 = *(const float4*)&Ac[kk][ty * 8 + 4];
            const longlong2* wp = (const longlong2*)&Wc[kk][tx * 8];
            longlong2 bA = wp[0], bB = wp[1];
            u64 ad[8] = { dup2(a0.x), dup2(a0.y), dup2(a0.z), dup2(a0.w),
                          dup2(a1.x), dup2(a1.y), dup2(a1.z), dup2(a1.w) };
            u64 bp[4] = { (u64)bA.x, (u64)bA.y, (u64)bB.x, (u64)bB.y };
#pragma unroll
            for (int i = 0; i < 8; i++)
#pragma unroll
                for (int j = 0; j < 4; j++) fma2(acc[i][j], ad[i], bp[j]);
        }
        if (more) { cp_wait<0>(); __syncthreads(); }
        buf ^= 1;
    }

    float cv[8][8];
#pragma unroll
    for (int i = 0; i < 8; i++)
#pragma unroll
        for (int jp = 0; jp < 4; jp++) up2(acc[i][jp], cv[i][jp * 2], cv[i][jp * 2 + 1]);

    if (OUTK) {
#pragma unroll
        for (int jn = 0; jn < 8; jn++) {
            int n = n0 + tx * 8 + jn;
            if (n < N) {
                float bb = bias[n];
                float4 o0, o1;
                o0.x = epi<ACT>(cv[0][jn] + bb); o0.y = epi<ACT>(cv[1][jn] + bb);
                o0.z = epi<ACT>(cv[2][jn] + bb); o0.w = epi<ACT>(cv[3][jn] + bb);
                o1.x = epi<ACT>(cv[4][jn] + bb); o1.y = epi<ACT>(cv[5][jn] + bb);
                o1.z = epi<ACT>(cv[6][jn] + bb); o1.w = epi<ACT>(cv[7][jn] + bb);
                size_t base = (size_t)n * M + m0 + ty * 8;
                *(float4*)(C + base)     = o0;
                *(float4*)(C + base + 4) = o1;
            }
        }
    } else {
#pragma unroll
        for (int i = 0; i < 8; i++) {
            size_t m = (size_t)(m0 + ty * 8 + i);
            float* crow = C + m * (size_t)N;
            int nb = n0 + tx * 8;
#pragma unroll
            for (int jn = 0; jn < 8; jn++) {
                int n = nb + jn;
                if (n < N) crow[n] = epi<ACT>(cv[i][jn] + bias[n]);
            }
        }
    }
}

// ---------------------------------------------------------------------------
// Fused output heads on K-major A with combined K-major head weights
// WTh[500][128] (cols 0..37 xm, 38..75 xs). Writes [b][t][38] into d_out.
// ---------------------------------------------------------------------------
__global__ __launch_bounds__(256, 2) void head_gemm(
    const float* __restrict__ AT, const float* __restrict__ WTh,
    const float* __restrict__ bm, const float* __restrict__ bs,
    float* __restrict__ Cm, float* __restrict__ Cs)
{
    __shared__ __align__(16) float As[2][8][128];
    __shared__ __align__(16) float Ws[2][8][128];
    const int tid = threadIdx.x;
    const int m0 = blockIdx.x * 128;
    const int tx = tid & 15, ty = tid >> 4;
    const int ka = tid >> 5, ca = (tid & 31) * 4;
    const int K = H_;

    u64 acc[8][4];
#pragma unroll
    for (int i = 0; i < 8; i++)
#pragma unroll
        for (int j = 0; j < 4; j++) acc[i][j] = 0ULL;

    auto issue = [&](int buf, int k0) {
        int k = k0 + ka;
        int kc = (k < K) ? k : (K - 1);
        int nb = (k < K) ? 16 : 0;
        cp16(&As[buf][ka][ca], AT + (size_t)kc * AM_ + m0 + ca, nb);
        cp16(&Ws[buf][ka][ca], WTh + (size_t)kc * 128 + ca, nb);
    };

    issue(0, 0); cp_commit();
    cp_wait<0>(); __syncthreads();

    const int nt = (K + 7) / 8;
    int buf = 0;
    for (int it = 0; it < nt; it++) {
        const bool more = (it + 1) < nt;
        if (more) { issue(buf ^ 1, (it + 1) * 8); cp_commit(); }
        const float (*Ac)[128] = As[buf];
        const float (*Wc)[128] = Ws[buf];
#pragma unroll
        for (int kk = 0; kk < 8; kk++) {
            float4 a0 = *(const float4*)&Ac[kk][ty * 8];
            float4 a1 = *(const float4*)&Ac[kk][ty * 8 + 4];
            const longlong2* wp = (const longlong2*)&Wc[kk][tx * 8];
            longlong2 bA = wp[0], bB = wp[1];
            u64 ad[8] = { dup2(a0.x), dup2(a0.y), dup2(a0.z), dup2(a0.w),
                          dup2(a1.x), dup2(a1.y), dup2(a1.z), dup2(a1.w) };
            u64 bp[4] = { (u64)bA.x, (u64)bA.y, (u64)bB.x, (u64)bB.y };
#pragma unroll
            for (int i = 0; i < 8; i++)
#pragma unroll
                for (int j = 0; j < 4; j++) fma2(acc[i][j], ad[i], bp[j]);
        }
        if (more) { cp_wait<0>(); __syncthreads(); }
        buf ^= 1;
    }

#pragma unroll
    for (int i = 0; i < 8; i++) {
        int mp = m0 + ty * 8 + i;
        int b = mp & 511, t = mp >> 9;
        size_t base = ((size_t)b * T_ + t) * 38;
#pragma unroll
        for (int jp = 0; jp < 4; jp++) {
            float c0v, c1v; up2(acc[i][jp], c0v, c1v);
            int nn = tx * 8 + jp * 2;
            if (nn < 38) {
                Cm[base + nn]     = c0v + bm[nn];
                Cm[base + nn + 1] = c1v + bm[nn + 1];
            } else if (nn < 76) {
                Cs[base + nn - 38] = softplusf(c0v + bs[nn - 38]) + 1e-4f;
                Cs[base + nn - 37] = softplusf(c1v + bs[nn - 37]) + 1e-4f;
            }
        }
    }
}

// ---------------------------------------------------------------------------
// GRU (R6 config + flag sync): persistent grid-stepped GEMM, SMEM weights,
// cp.async double-buffered h tiles (32k x 128b), 16 syncs/step.
// Grid 128 = 4 m-tiles x 32 j-tiles; CTA tile: 128 batch x 16 gate-triplets.
// Cross-CTA step sync: per-m-group release/acquire flags (no global barrier).
// ---------------------------------------------------------------------------
#define GRU_SMEM (48 * 512 + 2 * 32 * 132)   // floats

template<int DEC>
__global__ __launch_bounds__(256) void gru3(
    const float* __restrict__ gi_or_z,
    const float* __restrict__ Whh, const float* __restrict__ bhh,
    const float* __restrict__ wih, const float* __restrict__ bih,
    float* __restrict__ hout)
{
    extern __shared__ float smem[];
    float* sw = smem;                 // [48][512]   (g*16+jl)
    float* sA = smem + 48 * 512;      // [2][32][132]

    const int tid = threadIdx.x;
    const int jj  = tid >> 5;         // 0..7
    const int mg  = tid & 31;         // 0..31
    const int jt  = blockIdx.x & 31;
    const int mt  = blockIdx.x >> 5;
    const int j0  = jt * 16;
    const int m0  = mt * 128;
    const int jA  = j0 + jj * 2;
    const int jB  = jA + 1;
    const int lrow = tid >> 3;        // 0..31 staging row
    const int lcol = (tid & 7) * 16;  // staging col

    // ---- weights to smem (once); pads zero-filled ----
    for (int idx = tid; idx < 48 * 128; idx += 256) {
        int row = idx >> 7;            // g*16 + jl
        int k4  = (idx & 127) * 4;
        int g = row >> 4, jl = row & 15;
        int j = j0 + jl;
        float4 v = make_float4(0.f, 0.f, 0.f, 0.f);
        if (j < H_ && k4 < H_)
            v = *(const float4*)(Whh + ((size_t)(g * H_ + j)) * H_ + k4);
        *(float4*)&sw[row * 512 + k4] = v;
    }

    // ---- per-thread constants ----
    float brA = 0, bzA = 0, bnA = 0, brB = 0, bzB = 0, bnB = 0;
    float wA[9], wB[9], biA[3], biB[3];
#pragma unroll
    for (int i = 0; i < 9; i++) { wA[i] = 0.f; wB[i] = 0.f; }
#pragma unroll
    for (int i = 0; i < 3; i++) { biA[i] = 0.f; biB[i] = 0.f; }
    if (jA < H_) {
        brA = bhh[jA]; bzA = bhh[jA + H_]; bnA = bhh[jA + 2 * H_];
        if (DEC) {
            biA[0] = bih[jA]; biA[1] = bih[jA + H_]; biA[2] = bih[jA + 2 * H_];
#pragma unroll
            for (int d = 0; d < 3; d++) {
                wA[d]     = wih[(size_t)jA * 3 + d];
                wA[3 + d] = wih[(size_t)(jA + H_) * 3 + d];
                wA[6 + d] = wih[(size_t)(jA + 2 * H_) * 3 + d];
            }
        }
    }
    if (jB < H_) {
        brB = bhh[jB]; bzB = bhh[jB + H_]; bnB = bhh[jB + 2 * H_];
        if (DEC) {
            biB[0] = bih[jB]; biB[1] = bih[jB + H_]; biB[2] = bih[jB + 2 * H_];
#pragma unroll
            for (int d = 0; d < 3; d++) {
                wB[d]     = wih[(size_t)jB * 3 + d];
                wB[3 + d] = wih[(size_t)(jB + H_) * 3 + d];
                wB[6 + d] = wih[(size_t)(jB + 2 * H_) * 3 + d];
            }
        }
    }
    float hpA[4], hpB[4];
#pragma unroll
    for (int i = 0; i < 4; i++) { hpA[i] = 0.f; hpB[i] = 0.f; }
    __syncthreads();

    for (int t = 0; t < T_; t++) {
        // ---- prefetch input-gate values ig[jpair][gate][m] ----
        float ig[2][3][4];
        if (!DEC) {
            size_t off = (size_t)t * 512 + m0 + mg * 4;
#pragma unroll
            for (int g = 0; g < 3; g++) {
                float4 vA = (jA < H_) ? *(const float4*)(gi_or_z + (size_t)(g * H_ + jA) * AM_ + off)
                                      : make_float4(0.f, 0.f, 0.f, 0.f);
                float4 vB = (jB < H_) ? *(const float4*)(gi_or_z + (size_t)(g * H_ + jB) * AM_ + off)
                                      : make_float4(0.f, 0.f, 0.f, 0.f);
                ig[0][g][0] = vA.x; ig[0][g][1] = vA.y; ig[0][g][2] = vA.z; ig[0][g][3] = vA.w;
                ig[1][g][0] = vB.x; ig[1][g][1] = vB.y; ig[1][g][2] = vB.z; ig[1][g][3] = vB.w;
            }
        } else {
#pragma unroll
            for (int i = 0; i < 4; i++) {
                int b = m0 + mg * 4 + i;
                const float* zp = gi_or_z + ((size_t)b * T_ + t) * 3;
                float z0 = zp[0], z1 = zp[1], z2 = zp[2];
#pragma unroll
                for (int g = 0; g < 3; g++) {
                    ig[0][g][i] = biA[g] + wA[3 * g] * z0 + wA[3 * g + 1] * z1 + wA[3 * g + 2] * z2;
                    ig[1][g][i] = biB[g] + wB[3 * g] * z0 + wB[3 * g + 1] * z1 + wB[3 * g + 2] * z2;
                }
            }
        }

        u64 acc[2][3][2];
#pragma unroll
        for (int a = 0; a < 2; a++)
#pragma unroll
            for (int g = 0; g < 3; g++) { acc[a][g][0] = 0ULL; acc[a][g][1] = 0ULL; }

        if (t > 0) {
            // ---- wait for all 32 producers of my m-group to publish step t-1 ----
            if (tid < 32) {
                const unsigned* fp = &g_flag[(mt << 5) | tid];
                while (flag_load_acquire(fp) < (unsigned)t) __nanosleep(32);
            }
            __syncthreads();

            const float* Asrc = hout + (size_t)(t - 1) * 512 + m0;
            auto issueT = [&](int buf, int kt) {
                const float* p = Asrc + (size_t)(kt * 32 + lrow) * AM_ + lcol;
                float* q = &sA[buf * 32 * 132 + lrow * 132 + lcol];
                cp16(q,      p,      16);
                cp16(q + 4,  p + 4,  16);
                cp16(q + 8,  p + 8,  16);
                cp16(q + 12, p + 12, 16);
            };
            issueT(0, 0); cp_commit();
            cp_wait<0>(); __syncthreads();
            int buf = 0;
#pragma unroll 1
            for (int kt = 0; kt < 16; kt++) {
                const bool more = kt < 15;
                if (more) { issueT(buf ^ 1, kt + 1); cp_commit(); }
                const float* Ab = &sA[buf * 32 * 132];
#pragma unroll
                for (int kk = 0; kk < 32; kk += 4) {
                    int kb = kt * 32 + kk;
                    float4 w_r0 = *(const float4*)&sw[(jj * 2)      * 512 + kb];
                    float4 w_r1 = *(const float4*)&sw[(jj * 2 + 1)  * 512 + kb];
                    float4 w_z0 = *(const float4*)&sw[(16 + jj * 2)     * 512 + kb];
                    float4 w_z1 = *(const float4*)&sw[(16 + jj * 2 + 1) * 512 + kb];
                    float4 w_n0 = *(const float4*)&sw[(32 + jj * 2)     * 512 + kb];
                    float4 w_n1 = *(const float4*)&sw[(32 + jj * 2 + 1) * 512 + kb];
#pragma unroll
                    for (int i = 0; i < 4; i++) {
                        longlong2 hv = *(const longlong2*)&Ab[(kk + i) * 132 + mg * 4];
                        u64 h0 = (u64)hv.x, h1 = (u64)hv.y;
                        u64 d;
                        d = dup2(((const float*)&w_r0)[i]); fma2(acc[0][0][0], h0, d); fma2(acc[0][0][1], h1, d);
                        d = dup2(((const float*)&w_r1)[i]); fma2(acc[1][0][0], h0, d); fma2(acc[1][0][1], h1, d);
                        d = dup2(((const float*)&w_z0)[i]); fma2(acc[0][1][0], h0, d); fma2(acc[0][1][1], h1, d);
                        d = dup2(((const float*)&w_z1)[i]); fma2(acc[1][1][0], h0, d); fma2(acc[1][1][1], h1, d);
                        d = dup2(((const float*)&w_n0)[i]); fma2(acc[0][2][0], h0, d); fma2(acc[0][2][1], h1, d);
                        d = dup2(((const float*)&w_n1)[i]); fma2(acc[1][2][0], h0, d); fma2(acc[1][2][1], h1, d);
                    }
                }
                if (more) cp_wait<0>();
                __syncthreads();
                buf ^= 1;
            }
        }

        // ---- epilogue ----
        float aR[2][4], aZ[2][4], aN[2][4];
#pragma unroll
        for (int a = 0; a < 2; a++) {
            up2(acc[a][0][0], aR[a][0], aR[a][1]); up2(acc[a][0][1], aR[a][2], aR[a][3]);
            up2(acc[a][1][0], aZ[a][0], aZ[a][1]); up2(acc[a][1][1], aZ[a][2], aZ[a][3]);
            up2(acc[a][2][0], aN[a][0], aN[a][1]); up2(acc[a][2][1], aN[a][2], aN[a][3]);
        }
        size_t soff = (size_t)t * 512 + m0 + mg * 4;
        if (jA < H_) {
            float4 hv;
#pragma unroll
            for (int i = 0; i < 4; i++) {
                float r  = sigmoidf(ig[0][0][i] + aR[0][i] + brA);
                float zg = sigmoidf(ig[0][1][i] + aZ[0][i] + bzA);
                float n  = tanhf(ig[0][2][i] + r * (aN[0][i] + bnA));
                float hn = (1.f - zg) * n + zg * hpA[i];
                hpA[i] = hn;
                ((float*)&hv)[i] = hn;
            }
            *(float4*)(hout + (size_t)jA * AM_ + soff) = hv;
        }
        if (jB < H_) {
            float4 hv;
#pragma unroll
            for (int i = 0; i < 4; i++) {
                float r  = sigmoidf(ig[1][0][i] + aR[1][i] + brB);
                float zg = sigmoidf(ig[1][1][i] + aZ[1][i] + bzB);
                float n  = tanhf(ig[1][2][i] + r * (aN[1][i] + bnB));
                float hn = (1.f - zg) * n + zg * hpB[i];
                hpB[i] = hn;
                ((float*)&hv)[i] = hn;
            }
            *(float4*)(hout + (size_t)jB * AM_ + soff) = hv;
        }

        // ---- publish step t (release) ----
        if (t < T_ - 1) {
            __syncthreads();
            if (tid == 0) flag_store_release(&g_flag[blockIdx.x], (unsigned)(t + 1));
        }
    }
}

// ---------------------------------------------------------------------------
// Latent scan: one warp per batch element; hp row-major TB [t*512+b][500].
// ---------------------------------------------------------------------------
__global__ __launch_bounds__(128) void latent_kernel(
    const float* __restrict__ hp, const float* __restrict__ eps,
    const float* __restrict__ zmW, const float* __restrict__ zmb,
    const float* __restrict__ zsW, const float* __restrict__ zsb,
    float* __restrict__ out)
{
    __shared__ float s_m[3 * 503], s_s[3 * 503], s_mb[3], s_sb[3];
    const int tid = threadIdx.x;
    for (int i = tid; i < 3 * 503; i += 128) { s_m[i] = zmW[i]; s_s[i] = zsW[i]; }
    if (tid < 3) { s_mb[tid] = zmb[tid]; s_sb[tid] = zsb[tid]; }
    __syncthreads();

    const int warp = tid >> 5, lane = tid & 31;
    const int b = blockIdx.x * 4 + warp;
    if (b >= B_) return;

    float z0 = 0.f, z1 = 0.f, z2 = 0.f;
    float* zg = out + OFF_ZGEN;
    float* zm = out + OFF_ZMU;
    float* zs = out + OFF_ZSTD;

    for (int t = 0; t < T_; t++) {
        float m0 = 0.f, m1 = 0.f, m2 = 0.f, s0 = 0.f, s1 = 0.f, s2 = 0.f;
        const float* hrow = hp + ((size_t)t * 512 + b) * H_;
        for (int jj = lane; jj < 503; jj += 32) {
            float v = (jj < 500) ? hrow[jj] : (jj == 500 ? z0 : (jj == 501 ? z1 : z2));
            m0 += v * s_m[jj]; m1 += v * s_m[503 + jj]; m2 += v * s_m[1006 + jj];
            s0 += v * s_s[jj]; s1 += v * s_s[503 + jj]; s2 += v * s_s[1006 + jj];
        }
#pragma unroll
        for (int o = 16; o > 0; o >>= 1) {
            m0 += __shfl_xor_sync(0xffffffffu, m0, o);
            m1 += __shfl_xor_sync(0xffffffffu, m1, o);
            m2 += __shfl_xor_sync(0xffffffffu, m2, o);
            s0 += __shfl_xor_sync(0xffffffffu, s0, o);
            s1 += __shfl_xor_sync(0xffffffffu, s1, o);
            s2 += __shfl_xor_sync(0xffffffffu, s2, o);
        }
        m0 += s_mb[0]; m1 += s_mb[1]; m2 += s_mb[2];
        float st0 = softplusf(s0 + s_sb[0]) + 1e-4f;
        float st1 = softplusf(s1 + s_sb[1]) + 1e-4f;
        float st2 = softplusf(s2 + s_sb[2]) + 1e-4f;
        size_t er = ((size_t)b * T_ + t) * 3;
        float e0 = eps[er], e1 = eps[er + 1], e2 = eps[er + 2];
        z0 = m0 + st0 * e0; z1 = m1 + st1 * e1; z2 = m2 + st2 * e2;
        if (lane == 0) {
            zg[er] = z0; zg[er + 1] = z1; zg[er + 2] = z2;
            zm[er] = m0; zm[er + 1] = m1; zm[er + 2] = m2;
            zs[er] = st0; zs[er + 1] = st1; zs[er + 2] = st2;
        }
    }
}

// ---------------------------------------------------------------------------
// Planar flow stack
// ---------------------------------------------------------------------------
__global__ __launch_bounds__(256) void flow_kernel(
    const float* __restrict__ fw, const float* __restrict__ fb,
    const float* __restrict__ fu, float* __restrict__ out)
{
    __shared__ float sw[L_][3], su[L_][3], sb[L_], suw[L_];
    const int tid = threadIdx.x;
    if (tid < L_) {
        float w0 = fw[tid * 3], w1 = fw[tid * 3 + 1], w2 = fw[tid * 3 + 2];
        float u0 = fu[tid * 3], u1 = fu[tid * 3 + 1], u2 = fu[tid * 3 + 2];
        float wu = w0 * u0 + w1 * u1 + w2 * u2;
        float m = -1.f + softplusf(wu);
        float ww = w0 * w0 + w1 * w1 + w2 * w2 + 1e-7f;
        float c = (m - wu) / ww;
        sw[tid][0] = w0; sw[tid][1] = w1; sw[tid][2] = w2;
        su[tid][0] = u0 + c * w0; su[tid][1] = u1 + c * w1; su[tid][2] = u2 + c * w2;
        sb[tid] = fb[tid];
        suw[tid] = su[tid][0] * w0 + su[tid][1] * w1 + su[tid][2] * w2;
    }
    __syncthreads();
    int idx = blockIdx.x * 256 + tid;
    if (idx >= BT_) return;
    const float* zg = out + OFF_ZGEN;
    float z0 = zg[idx * 3], z1 = zg[idx * 3 + 1], z2 = zg[idx * 3 + 2];
    float ld = 0.f;
#pragma unroll
    for (int l = 0; l < L_; l++) {
        float lin = z0 * sw[l][0] + z1 * sw[l][1] + z2 * sw[l][2] + sb[l];
        float th = tanhf(lin);
        z0 += su[l][0] * th; z1 += su[l][1] * th; z2 += su[l][2] * th;
        float det = 1.f + (1.f - th * th) * suw[l];
        ld += logf(fabsf(det) + 1e-7f);
    }
    float* zf = out + OFF_ZFIN;
    zf[idx * 3] = z0; zf[idx * 3 + 1] = z1; zf[idx * 3 + 2] = z2;
    out[OFF_LDJ + idx] = ld;
}

// ---------------------------------------------------------------------------
// Launch
// ---------------------------------------------------------------------------
extern "C" void kernel_launch(void* const* d_in, const int* in_sizes, int n_in,
                              void* d_out, int out_size) {
    (void)in_sizes; (void)n_in; (void)out_size;
    const float* x        = (const float*)d_in[0];
    const float* eps      = (const float*)d_in[1];
    const float* enc_Wih  = (const float*)d_in[2];
    const float* enc_Whh  = (const float*)d_in[3];
    const float* enc_bih  = (const float*)d_in[4];
    const float* enc_bhh  = (const float*)d_in[5];
    const float* enc_W1   = (const float*)d_in[6];
    const float* enc_b1   = (const float*)d_in[7];
    const float* enc_W2   = (const float*)d_in[8];
    const float* enc_b2   = (const float*)d_in[9];
    const float* zm_W     = (const float*)d_in[10];
    const float* zm_b     = (const float*)d_in[11];
    const float* zs_W     = (const float*)d_in[12];
    const float* zs_b     = (const float*)d_in[13];
    const float* flow_w   = (const float*)d_in[14];
    const float* flow_b   = (const float*)d_in[15];
    const float* flow_u   = (const float*)d_in[16];
    const float* dec_Wih  = (const float*)d_in[17];
    const float* dec_Whh  = (const float*)d_in[18];
    const float* dec_bih  = (const float*)d_in[19];
    const float* dec_bhh  = (const float*)d_in[20];
    const float* dec_W1   = (const float*)d_in[21];
    const float* dec_b1   = (const float*)d_in[22];
    const float* dec_W2   = (const float*)d_in[23];
    const float* dec_b2   = (const float*)d_in[24];
    const float* xm_W     = (const float*)d_in[25];
    const float* xm_b     = (const float*)d_in[26];
    const float* xs_W     = (const float*)d_in[27];
    const float* xs_b     = (const float*)d_in[28];
    float* out = (float*)d_out;

    float *xT, *gi, *hK, *t1, *hp, *wtgi, *wt1, *wt2, *wt3, *wt4, *wth;
    unsigned* flg;
    cudaGetSymbolAddress((void**)&xT,   g_xT);
    cudaGetSymbolAddress((void**)&gi,   g_gi);
    cudaGetSymbolAddress((void**)&hK,   g_hK);
    cudaGetSymbolAddress((void**)&t1,   g_t1);
    cudaGetSymbolAddress((void**)&hp,   g_hp);
    cudaGetSymbolAddress((void**)&wtgi, g_wtgi);
    cudaGetSymbolAddress((void**)&wt1,  g_wt1);
    cudaGetSymbolAddress((void**)&wt2,  g_wt2);
    cudaGetSymbolAddress((void**)&wt3,  g_wt3);
    cudaGetSymbolAddress((void**)&wt4,  g_wt4);
    cudaGetSymbolAddress((void**)&wth,  g_wth);
    cudaGetSymbolAddress((void**)&flg,  g_flag);

    const size_t gru_smem = GRU_SMEM * sizeof(float);
    cudaFuncSetAttribute(gru3<0>, cudaFuncAttributeMaxDynamicSharedMemorySize, (int)gru_smem);
    cudaFuncSetAttribute(gru3<1>, cudaFuncAttributeMaxDynamicSharedMemorySize, (int)gru_smem);

    // zero k-pad rows 500..511 of h history
    cudaMemsetAsync(hK + (size_t)H_ * AM_, 0, (size_t)12 * AM_ * sizeof(float));

    // ---- all weight transposes in one launch + x transpose ----
    transpose_all<<<dim3(16, 47, 7), dim3(32, 8)>>>(
        enc_Wih, enc_W1, enc_W2, dec_W1, dec_W2, xm_W, xs_W,
        wtgi, wt1, wt2, wt3, wt4, wth);
    transpose_x<<<(X_ * AM_ + 255) / 256, 256>>>(x, xT);

    // ---- Encoder ----
    gemm2t<0, 1><<<dim3(400, 12), 256>>>(xT, wtgi, enc_bih, gi, AM_, G_, X_, 1536);
    cudaMemsetAsync(flg, 0, 128 * sizeof(unsigned));
    gru3<0><<<128, 256, gru_smem>>>(gi, enc_Whh, enc_bhh, nullptr, nullptr, hK);
    gemm2t<1, 1><<<dim3(400, 4), 256>>>(hK, wt1, enc_b1, t1, AM_, H_, H_, 512);
    gemm2t<1, 0><<<dim3(400, 4), 256>>>(t1, wt2, enc_b2, hp, AM_, H_, H_, 512);

    // ---- Latent scan + flows ----
    latent_kernel<<<128, 128>>>(hp, eps, zm_W, zm_b, zs_W, zs_b, out);
    flow_kernel<<<200, 256>>>(flow_w, flow_b, flow_u, out);

    // ---- Decoder (input gates inline from z_fin) ----
    cudaMemsetAsync(flg, 0, 128 * sizeof(unsigned));
    gru3<1><<<128, 256, gru_smem>>>(out + OFF_ZFIN, dec_Whh, dec_bhh, dec_Wih, dec_bih, hK);
    gemm2t<1, 1><<<dim3(400, 4), 256>>>(hK, wt3, dec_b1, t1, AM_, H_, H_, 512);
    gemm2t<1, 1><<<dim3(400, 4), 256>>>(t1, wt4, dec_b2, hp, AM_, H_, H_, 512);

    // ---- Output heads ----
    head_gemm<<<400, 256>>>(hp, wth, xm_b, xs_b, out + OFF_XMU, out + OFF_XSTD);
}